// round 13
// baseline (speedup 1.0000x reference)
#include <cuda_runtime.h>
#include <float.h>

#define S    8192
#define D    1024
#define E    64
#define CAP  256
#define NTILE 256    /* S/32 tiles for rank/scan  */
#define NBLK  128    /* gate blocks               */
#define FBLK  4096   /* fill blocks (256KB each)  */
#define SCANB 128    /* scan block id             */
#define SCAT0 129    /* first scatter block       */
#define NSCAT 32     /* scatter blocks            */
#define FILL0 161    /* first fill block          */
#define TOTBLK (FILL0 + FBLK)   /* 4257 */

static const size_t OFF_CW  = 1ULL;
static const size_t OFF_DM  = 1ULL + 134217728ULL;   /* 134217729 */
static const size_t OFF_EXP = 1ULL + 268435456ULL;   /* 268435457 */
static const size_t OFF_ORG = 268435521ULL;          /* OFF_EXP + 64 */

/* total float8s in [8, 268435456) */
#define NV8 33554431ULL

/* ---------------- scratch (device globals; no allocs) ---------------- */
__device__ int   d_idx1[S];
__device__ int   d_idx2[S];
__device__ float d_g1[S];
__device__ float d_g2[S];
__device__ int   d_cnt1[NTILE * E];
__device__ int   d_cnt2[NTILE * E];
__device__ int   d_off1[NTILE * E];
__device__ int   d_off2[NTILE * E];
__device__ int   d_total1[E];
__device__ float d_mepart[NBLK * E];
/* sync state: zero-initialized at load; self-reset by last exiting block */
__device__ int   g_gate_done;
__device__ int   g_scan_flag;
__device__ int   g_fill_done;
__device__ int   g_all_done;

#define TB 64   /* tokens per gate block */
#define KC 32   /* K chunk */

__device__ __forceinline__ void st_v8_zero(float* p) {
    const float z = 0.f;
    asm volatile(
        "st.global.v8.f32 [%0], {%1,%2,%3,%4,%5,%6,%7,%8};"
        :: "l"(p), "f"(z), "f"(z), "f"(z), "f"(z),
           "f"(z), "f"(z), "f"(z), "f"(z)
        : "memory");
}

__global__ __launch_bounds__(256) void mega_kernel(
    const float* __restrict__ x, const float* __restrict__ wg,
    float* __restrict__ out)
{
    /* overlay: xs[64][32]=sbuf[0..2048), ws[32][64]=sbuf[2048..4096),
       ls[64][64] overlays sbuf after the gemm loop. */
    __shared__ float sbuf[4096];
    __shared__ float me_w[8][E];
    __shared__ int   cnt1_s[2][E];
    __shared__ int   cnt2_s[2][E];
    __shared__ float red2[2];

    const int b   = blockIdx.x;
    const int tid = threadIdx.x;

    if (b >= FILL0) {
        /* ================= FILL (STG.256) ===========================
           v8 region = floats [8, 268435456) exactly (NV8 float8s).
           Block fb owns float8s [fb*8192, (fb+1)*8192); the last block
           predicates off its final v8 (index NV8) and writes nothing
           outside the cw/dm region. exp_counts is never touched here. */
        const int fb = b - FILL0;
        float* base = out + 8 + ((size_t)fb * 8192 + tid) * 8;
        if (fb < FBLK - 1) {
#pragma unroll
            for (int k = 0; k < 32; k++)
                st_v8_zero(base + (size_t)k * 2048);
        } else {
#pragma unroll
            for (int k = 0; k < 32; k++) {
                size_t idx = (size_t)fb * 8192 + tid + (size_t)k * 256;
                if (idx < NV8) st_v8_zero(base + (size_t)k * 2048);
            }
            /* tail float: out[268435456] (last element of dm region) */
            if (tid == 0) out[268435456] = 0.f;
        }
        if (fb == 0 && tid >= 1 && tid < 8) out[tid] = 0.f;
        __syncthreads();
        if (tid == 0) { __threadfence(); atomicAdd(&g_fill_done, 1); }
    }
    else if (b < NBLK) {
        /* ================= GATE ===================================== */
        float (*xs)[KC] = reinterpret_cast<float (*)[KC]>(sbuf);
        float (*ws)[E]  = reinterpret_cast<float (*)[E]>(sbuf + 2048);
        float (*ls)[E]  = reinterpret_cast<float (*)[E]>(sbuf);

        float* __restrict__ org = out + OFF_ORG;
        const int s0 = b * TB;

        if (tid < E) {
            cnt1_s[0][tid] = 0; cnt1_s[1][tid] = 0;
            cnt2_s[0][tid] = 0; cnt2_s[1][tid] = 0;
        }

        const int tx = tid & 15;
        const int ty = tid >> 4;

        float acc[4][4];
#pragma unroll
        for (int i = 0; i < 4; i++)
#pragma unroll
            for (int j = 0; j < 4; j++) acc[i][j] = 0.f;

        for (int k0 = 0; k0 < D; k0 += KC) {
            __syncthreads();
#pragma unroll
            for (int j = 0; j < 2; j++) {
                int i  = tid + j * 256;
                int t  = i >> 3, k4 = (i & 7) * 4;
                float4 v = __ldcs(reinterpret_cast<const float4*>(
                                 x + (size_t)(s0 + t) * D + k0 + k4));
                *reinterpret_cast<float4*>(&xs[t][k4]) = v;
            }
#pragma unroll
            for (int j = 0; j < 2; j++) {
                int i  = tid + j * 256;
                int k  = i >> 4, e4 = (i & 15) * 4;
                float4 v = *reinterpret_cast<const float4*>(
                                 wg + (size_t)(k0 + k) * E + e4);
                *reinterpret_cast<float4*>(&ws[k][e4]) = v;
            }
            __syncthreads();
#pragma unroll
            for (int k = 0; k < KC; k += 4) {
                float xv[4][4], wv[4][4];
#pragma unroll
                for (int i = 0; i < 4; i++) {
                    float4 t4 = *reinterpret_cast<const float4*>(&xs[ty * 4 + i][k]);
                    xv[i][0] = t4.x; xv[i][1] = t4.y; xv[i][2] = t4.z; xv[i][3] = t4.w;
                }
#pragma unroll
                for (int kk = 0; kk < 4; kk++) {
                    float4 t4 = *reinterpret_cast<const float4*>(&ws[k + kk][tx * 4]);
                    wv[kk][0] = t4.x; wv[kk][1] = t4.y; wv[kk][2] = t4.z; wv[kk][3] = t4.w;
                }
#pragma unroll
                for (int i = 0; i < 4; i++)
#pragma unroll
                    for (int j = 0; j < 4; j++)
#pragma unroll
                        for (int kk = 0; kk < 4; kk++)
                            acc[i][j] += xv[i][kk] * wv[kk][j];
            }
        }

        __syncthreads();
#pragma unroll
        for (int i = 0; i < 4; i++) {
            float4 t4 = make_float4(acc[i][0], acc[i][1], acc[i][2], acc[i][3]);
            *reinterpret_cast<float4*>(&ls[ty * 4 + i][tx * 4]) = t4;
        }
        __syncthreads();

        const int lane = tid & 31;
        const int warp = tid >> 5;
        const unsigned FULL = 0xffffffffu;
        float me0 = 0.f, me1 = 0.f;

        for (int tt = 0; tt < 8; tt++) {
            int t = warp * 8 + tt;
            float v0 = ls[t][lane];
            float v1 = ls[t][lane + 32];

            float m; int mi;
            if (v1 > v0) { m = v1; mi = lane + 32; } else { m = v0; mi = lane; }
#pragma unroll
            for (int off = 16; off; off >>= 1) {
                float om = __shfl_xor_sync(FULL, m, off);
                int  omi = __shfl_xor_sync(FULL, mi, off);
                if (om > m || (om == m && omi < mi)) { m = om; mi = omi; }
            }
            int idx1 = mi; float mx = m;

            float e0 = __expf(v0 - mx), e1 = __expf(v1 - mx);
            float sum = e0 + e1;
#pragma unroll
            for (int off = 16; off; off >>= 1) sum += __shfl_xor_sync(FULL, sum, off);
            float inv = 1.f / sum;
            float g0 = e0 * inv, g1 = e1 * inv;

            int sg = s0 + t;
            org[(size_t)sg * E + lane]      = g0;
            org[(size_t)sg * E + lane + 32] = g1;
            me0 += g0; me1 += g1;

            float u0 = (lane == idx1)      ? -FLT_MAX : v0;
            float u1 = (lane + 32 == idx1) ? -FLT_MAX : v1;
            if (u1 > u0) { m = u1; mi = lane + 32; } else { m = u0; mi = lane; }
#pragma unroll
            for (int off = 16; off; off >>= 1) {
                float om = __shfl_xor_sync(FULL, m, off);
                int  omi = __shfl_xor_sync(FULL, mi, off);
                if (om > m || (om == m && omi < mi)) { m = om; mi = omi; }
            }
            int idx2 = mi;

            float c1  = (idx1 < 32) ? g0 : g1;
            float gt1 = __shfl_sync(FULL, c1, idx1 & 31);
            float c2  = (idx2 < 32) ? g0 : g1;
            float gt2 = __shfl_sync(FULL, c2, idx2 & 31);

            if (lane == 0) {
                d_idx1[sg] = idx1; d_idx2[sg] = idx2;
                d_g1[sg] = gt1;    d_g2[sg] = gt2;
                int half = t >> 5;
                atomicAdd(&cnt1_s[half][idx1], 1);
                atomicAdd(&cnt2_s[half][idx2], 1);
            }
        }
        me_w[warp][lane]      = me0;
        me_w[warp][lane + 32] = me1;
        __syncthreads();

        if (tid < E) {
            float sm = 0.f;
#pragma unroll
            for (int w = 0; w < 8; w++) sm += me_w[w][tid];
            d_mepart[b * E + tid] = sm;
            d_cnt1[(b * 2 + 0) * E + tid] = cnt1_s[0][tid];
            d_cnt1[(b * 2 + 1) * E + tid] = cnt1_s[1][tid];
            d_cnt2[(b * 2 + 0) * E + tid] = cnt2_s[0][tid];
            d_cnt2[(b * 2 + 1) * E + tid] = cnt2_s[1][tid];
        }
        __syncthreads();
        if (tid == 0) { __threadfence(); atomicAdd(&g_gate_done, 1); }
    }
    else if (b == SCANB) {
        /* ================= SCAN (spins on gate) =====================
           writes l_aux AND exp_counts directly (fill never touches
           the exp_counts region anymore). */
        if (tid == 0) {
            while (atomicAdd(&g_gate_done, 0) < NBLK) __nanosleep(64);
        }
        __syncthreads();
        __threadfence();

        if (tid < E) {
            const int e = tid;
            int run1 = 0, run2 = 0;
            for (int t0 = 0; t0 < NTILE; t0 += 16) {
                int c1[16], c2[16];
#pragma unroll
                for (int j = 0; j < 16; j++) {
                    c1[j] = __ldcg(&d_cnt1[(t0 + j) * E + e]);
                    c2[j] = __ldcg(&d_cnt2[(t0 + j) * E + e]);
                }
#pragma unroll
                for (int j = 0; j < 16; j++) {
                    d_off1[(t0 + j) * E + e] = run1; run1 += c1[j];
                    d_off2[(t0 + j) * E + e] = run2; run2 += c2[j];
                }
            }
            d_total1[e] = run1;
            out[OFF_EXP + e] = (float)(run1 + run2);

            float mesum = 0.f;
            for (int b0 = 0; b0 < NBLK; b0 += 16) {
                float mv[16];
#pragma unroll
                for (int j = 0; j < 16; j++) mv[j] = __ldcg(&d_mepart[(b0 + j) * E + e]);
#pragma unroll
                for (int j = 0; j < 16; j++) mesum += mv[j];
            }
            float p = (mesum / 8192.f) * ((float)run1 / 8192.f);
#pragma unroll
            for (int off = 16; off; off >>= 1)
                p += __shfl_xor_sync(0xffffffffu, p, off);
            if ((e & 31) == 0) red2[e >> 5] = p;
        }
        __syncthreads();
        if (tid == 0) {
            out[0] = (red2[0] + red2[1]) * 4096.f;   /* l_aux * E*E */
            __threadfence();
            atomicExch(&g_scan_flag, 1);
        }
    }
    else {
        /* ================= SCATTER ==================================
           Wait for scan, PRECOMPUTE all values/addresses, then wait
           for fill, then issue only the final stores. */
        const int sb = b - SCAT0;
        if (tid == 0) {
            while (atomicAdd(&g_scan_flag, 0) == 0) __nanosleep(64);
        }
        __syncthreads();
        __threadfence();

        float* __restrict__ cw = out + OFF_CW;
        float* __restrict__ dm = out + OFF_DM;

        const int lane = tid & 31;
        const int warp = tid >> 5;
        const int tile = sb * 8 + warp;   /* 32 blocks x 8 warps = 256 tiles */
        const int s = tile * 32 + lane;
        const unsigned FULL = 0xffffffffu;
        const unsigned ltmask = (1u << lane) - 1u;

        int e1 = __ldcg(&d_idx1[s]), e2 = __ldcg(&d_idx2[s]);
        unsigned mm1 = __match_any_sync(FULL, e1);
        int loc1 = __ldcg(&d_off1[tile * E + e1]) + __popc(mm1 & ltmask);
        unsigned mm2 = __match_any_sync(FULL, e2);
        int loc2 = __ldcg(&d_off2[tile * E + e2]) + __popc(mm2 & ltmask)
                 + __ldcg(&d_total1[e2]);

        bool k1 = loc1 < CAP, k2 = loc2 < CAP;
        float g1 = k1 ? __ldcg(&d_g1[s]) : 0.f;
        float g2 = k2 ? __ldcg(&d_g2[s]) : 0.f;
        float denom = fmaxf(g1 + g2, 1.1920929e-07f);   /* fp32 eps */
        float w1 = g1 / denom, w2 = g2 / denom;
        size_t o1 = (size_t)s * (E * CAP) + (size_t)e1 * CAP + loc1;
        size_t o2 = (size_t)s * (E * CAP) + (size_t)e2 * CAP + loc2;
        float m1 = (w1 != 0.f) ? 1.f : 0.f;
        float m2 = (w2 != 0.f) ? 1.f : 0.f;

        /* everything is in registers; now wait for the fill to finish */
        if (tid == 0) {
            while (atomicAdd(&g_fill_done, 0) < FBLK) __nanosleep(128);
        }
        __syncthreads();
        __threadfence();

        if (k1) { cw[o1] = w1; dm[o1] = m1; }
        if (k2) { cw[o2] = w2; dm[o2] = m2; }
    }

    /* ========== epilogue: last exiting block resets sync state ======= */
    __syncthreads();
    if (tid == 0) {
        if (atomicAdd(&g_all_done, 1) == TOTBLK - 1) {
            atomicExch(&g_gate_done, 0);
            atomicExch(&g_scan_flag, 0);
            atomicExch(&g_fill_done, 0);
            atomicExch(&g_all_done, 0);
        }
    }
}

/* ---------------- launch: ONE kernel ---------------------------------- */
extern "C" void kernel_launch(void* const* d_in, const int* in_sizes, int n_in,
                              void* d_out, int out_size) {
    const float* x  = (const float*)d_in[0];
    const float* wg = (const float*)d_in[1];
    float* out = (float*)d_out;
    mega_kernel<<<TOTBLK, 256>>>(x, wg, out);
}